// round 1
// baseline (speedup 1.0000x reference)
#include <cuda_runtime.h>
#include <cstdint>

#define NN   512
#define JJ   48
#define MM   16
#define MIDC 128
#define EE   (NN*JJ)
#define EPSL 1e-5f
#define NPAD 264

// ---------------- device scratch ----------------
__device__ int g_mask_mode;                       // 0 = 1-byte bool, 1 = float32, 2 = int32
__device__ __align__(16) float g_h2[4u * EE * MIDC];   // ~50 MB

// ---------------- K0: mask dtype detection ----------------
__global__ void k0_detect(const unsigned char* __restrict__ mb) {
    __shared__ int c1, c3;
    if (threadIdx.x == 0) { c1 = 0; c3 = 0; }
    __syncthreads();
    int l1 = 0, l3 = 0;
    for (int i = threadIdx.x * 4; i < EE; i += blockDim.x * 4) {
        if (mb[i + 1]) l1++;                 // nonzero high-ish byte => 1-byte mask
        if (mb[i + 3] == 0x3Fu) l3++;        // 0x3F top byte => float 1.0f
    }
    if (l1) atomicAdd(&c1, l1);
    if (l3) atomicAdd(&c3, l3);
    __syncthreads();
    if (threadIdx.x == 0) g_mask_mode = c1 ? 0 : (c3 ? 1 : 2);
}

// ---------------- K1: per-edge radial MLP (w1->LN->relu->w2->LN->relu) ----------------
__global__ __launch_bounds__(256) void k1_mlp(
    const float* __restrict__ rel,
    const float* __restrict__ w1, const float* __restrict__ b1,
    const float* __restrict__ g1, const float* __restrict__ be1,
    const float* __restrict__ w2, const float* __restrict__ b2,
    const float* __restrict__ g2, const float* __restrict__ be2)
{
    __shared__ float h1s[32][MIDC];
    const int t = threadIdx.x, lane = t & 31, wp = t >> 5;
    const int e0 = blockIdx.x * 32;
    const int cg = t & 31, rg = t >> 5;

    for (int p = 0; p < 4; ++p) {
        const float* w1p = w1 + p * MIDC;  const float* b1p = b1 + p * MIDC;
        const float* g1p = g1 + p * MIDC;  const float* be1p = be1 + p * MIDC;

        // Phase A: h1 for 4 edges owned by this warp (warp-private rows)
        #pragma unroll
        for (int q = 0; q < 4; ++q) {
            const int le = wp * 4 + q;
            const float d = rel[e0 + le];
            float a[4];
            #pragma unroll
            for (int s_ = 0; s_ < 4; ++s_) {
                int c = lane + 32 * s_;
                a[s_] = fmaf(d, w1p[c], b1p[c]);
            }
            float s = a[0] + a[1] + a[2] + a[3];
            float s2 = a[0]*a[0] + a[1]*a[1] + a[2]*a[2] + a[3]*a[3];
            #pragma unroll
            for (int off = 16; off; off >>= 1) {
                s  += __shfl_xor_sync(0xffffffffu, s,  off);
                s2 += __shfl_xor_sync(0xffffffffu, s2, off);
            }
            const float mu  = s * 0.0078125f;
            const float inv = rsqrtf(fmaf(-mu, mu, s2 * 0.0078125f) + EPSL);
            #pragma unroll
            for (int s_ = 0; s_ < 4; ++s_) {
                int c = lane + 32 * s_;
                h1s[le][c] = fmaxf(fmaf((a[s_] - mu) * inv, g1p[c], be1p[c]), 0.f);
            }
        }
        __syncwarp();

        // Phase B: h2 = relu(LN(h1 @ w2 + b2)); warp rg owns rows rg*4..rg*4+3
        float acc[4][4];
        #pragma unroll
        for (int q = 0; q < 4; ++q)
            acc[q][0] = acc[q][1] = acc[q][2] = acc[q][3] = 0.f;
        const float4* w2p = (const float4*)(w2 + p * MIDC * MIDC);
        #pragma unroll 4
        for (int k = 0; k < MIDC; ++k) {
            float4 wv = w2p[k * 32 + cg];
            #pragma unroll
            for (int q = 0; q < 4; ++q) {
                float av = h1s[rg * 4 + q][k];
                acc[q][0] = fmaf(av, wv.x, acc[q][0]);
                acc[q][1] = fmaf(av, wv.y, acc[q][1]);
                acc[q][2] = fmaf(av, wv.z, acc[q][2]);
                acc[q][3] = fmaf(av, wv.w, acc[q][3]);
            }
        }
        const float4 b2v  = ((const float4*)(b2  + p * MIDC))[cg];
        const float4 g2v  = ((const float4*)(g2  + p * MIDC))[cg];
        const float4 be2v = ((const float4*)(be2 + p * MIDC))[cg];
        #pragma unroll
        for (int q = 0; q < 4; ++q) {
            float v0 = acc[q][0] + b2v.x, v1 = acc[q][1] + b2v.y;
            float v2 = acc[q][2] + b2v.z, v3 = acc[q][3] + b2v.w;
            float s  = v0 + v1 + v2 + v3;
            float s2 = v0*v0 + v1*v1 + v2*v2 + v3*v3;
            #pragma unroll
            for (int off = 16; off; off >>= 1) {
                s  += __shfl_xor_sync(0xffffffffu, s,  off);
                s2 += __shfl_xor_sync(0xffffffffu, s2, off);
            }
            const float mu  = s * 0.0078125f;
            const float inv = rsqrtf(fmaf(-mu, mu, s2 * 0.0078125f) + EPSL);
            float4 o;
            o.x = fmaxf(fmaf((v0 - mu) * inv, g2v.x, be2v.x), 0.f);
            o.y = fmaxf(fmaf((v1 - mu) * inv, g2v.y, be2v.y), 0.f);
            o.z = fmaxf(fmaf((v2 - mu) * inv, g2v.z, be2v.z), 0.f);
            o.w = fmaxf(fmaf((v3 - mu) * inv, g2v.w, be2v.w), 0.f);
            ((float4*)(g_h2 + ((size_t)p * EE + e0 + rg * 4 + q) * MIDC))[cg] = o;
        }
        __syncwarp();
    }
}

// ---------------- K2 helpers: register-tiled GEMMs into smem R ----------------
__device__ __forceinline__ void gemm256(const float* __restrict__ w3, const float* __restrict__ b3,
                                        const float* h2p, float* Rb, int t)
{
    const int cg = t & 63, rg = t >> 6;            // 64 col-groups x 4 row-groups (12 rows each)
    float acc[12][4];
    #pragma unroll
    for (int q = 0; q < 12; ++q)
        acc[q][0] = acc[q][1] = acc[q][2] = acc[q][3] = 0.f;
    const float4* w4 = (const float4*)w3;
    #pragma unroll 2
    for (int k = 0; k < MIDC; ++k) {
        float4 wv = w4[k * 64 + cg];
        #pragma unroll
        for (int q = 0; q < 12; ++q) {
            float av = h2p[(rg * 12 + q) * MIDC + k];
            acc[q][0] = fmaf(av, wv.x, acc[q][0]);
            acc[q][1] = fmaf(av, wv.y, acc[q][1]);
            acc[q][2] = fmaf(av, wv.z, acc[q][2]);
            acc[q][3] = fmaf(av, wv.w, acc[q][3]);
        }
    }
    const float4 bv = ((const float4*)b3)[cg];
    #pragma unroll
    for (int q = 0; q < 12; ++q) {
        float* r = Rb + (rg * 12 + q) * NPAD + cg * 4;
        r[0] = acc[q][0] + bv.x; r[1] = acc[q][1] + bv.y;
        r[2] = acc[q][2] + bv.z; r[3] = acc[q][3] + bv.w;
    }
}

__device__ __forceinline__ void gemm192(const float* __restrict__ w3, const float* __restrict__ b3,
                                        const float* h2p, float* Rb, int t)
{
    if (t >= 192) return;
    const int cg = t % 48, rg = t / 48;            // 48 col-groups x 4 row-groups (12 rows each)
    float acc[12][4];
    #pragma unroll
    for (int q = 0; q < 12; ++q)
        acc[q][0] = acc[q][1] = acc[q][2] = acc[q][3] = 0.f;
    #pragma unroll 2
    for (int k = 0; k < MIDC; ++k) {
        float4 wv = *(const float4*)(w3 + k * 768 + cg * 4);
        #pragma unroll
        for (int q = 0; q < 12; ++q) {
            float av = h2p[(rg * 12 + q) * MIDC + k];
            acc[q][0] = fmaf(av, wv.x, acc[q][0]);
            acc[q][1] = fmaf(av, wv.y, acc[q][1]);
            acc[q][2] = fmaf(av, wv.z, acc[q][2]);
            acc[q][3] = fmaf(av, wv.w, acc[q][3]);
        }
    }
    const float4 bv = *(const float4*)(b3 + cg * 4);
    #pragma unroll
    for (int q = 0; q < 12; ++q) {
        float* r = Rb + (rg * 12 + q) * NPAD + cg * 4;
        r[0] = acc[q][0] + bv.x; r[1] = acc[q][1] + bv.y;
        r[2] = acc[q][2] + bv.z; r[3] = acc[q][3] + bv.w;
    }
}

// ---------------- K2: per-node conv (R on the fly, fused contraction) ----------------
// dyn smem layout (floats):
//  h2s [4][48][128] @ 0      (24576)
//  Rbuf[48][NPAD]   @ 24576  (12672)
//  s11m[9][48][16]  @ 37248  (6912)   ((a*3+fi)*48+j)*16+i
//  xg0m[48][16]     @ 44160  (768)
//  xg1s[48][48]     @ 44928  (2304)
//  t10m[48][16]     @ 47232  (768)
//  v01s[48][3]      @ 48000  (144)
//  c00s[48]         @ 48144
//  mskf[48]         @ 48192
//  acc0[16]         @ 48240
//  acc1[48]         @ 48256
//  dnm [1]          @ 48304
#define K2_SMEM_FLOATS 48320

__global__ __launch_bounds__(256) void k2_conv(
    const float* __restrict__ x0, const float* __restrict__ x1,
    const int* __restrict__ nidx, const void* __restrict__ maskp,
    const float* __restrict__ b00, const float* __restrict__ b01,
    const float* __restrict__ b10, const float* __restrict__ b11,
    const float* __restrict__ w3_00, const float* __restrict__ b3_00,
    const float* __restrict__ w3_01, const float* __restrict__ b3_01,
    const float* __restrict__ w3_10, const float* __restrict__ b3_10,
    const float* __restrict__ w3_11, const float* __restrict__ b3_11,
    const float* __restrict__ ks0, const float* __restrict__ ks1,
    float* __restrict__ out)
{
    extern __shared__ float sm[];
    float* h2s  = sm;
    float* Rbuf = sm + 24576;
    float* s11m = sm + 37248;
    float* xg0m = sm + 44160;
    float* xg1s = sm + 44928;
    float* t10m = sm + 47232;
    float* v01s = sm + 48000;
    float* c00s = sm + 48144;
    float* mskf = sm + 48192;
    float* acc0 = sm + 48240;
    float* acc1 = sm + 48256;
    float* dnm  = sm + 48304;

    const int n = blockIdx.x;
    const int t = threadIdx.x;
    const int base = n * JJ;

    // ---- phase 0a: masks, gathers, basis scalars, h2 tile copy ----
    if (t < 64) { if (t < 16) acc0[t] = 0.f; else acc1[t - 16] = 0.f; }
    if (t < 48) {
        const int j = t;
        const int mode = g_mask_mode;
        float mf;
        if (mode == 0)       mf = ((const unsigned char*)maskp)[base + j] ? 1.f : 0.f;
        else if (mode == 1)  mf = (((const float*)maskp)[base + j] != 0.f) ? 1.f : 0.f;
        else                 mf = ((const int*)maskp)[base + j] ? 1.f : 0.f;
        mskf[j] = mf;
        const int nb = nidx[base + j];
        #pragma unroll
        for (int i = 0; i < 16; ++i) xg0m[j * 16 + i] = mf * x0[nb * 16 + i];
        const float* xs = x1 + nb * 48;
        #pragma unroll
        for (int ib = 0; ib < 48; ++ib) xg1s[j * 48 + ib] = xs[ib];
        c00s[j] = b00[base + j];
        v01s[j * 3 + 0] = b01[(base + j) * 3 + 0];
        v01s[j * 3 + 1] = b01[(base + j) * 3 + 1];
        v01s[j * 3 + 2] = b01[(base + j) * 3 + 2];
    }
    for (int p = 0; p < 4; ++p) {
        const float4* s4 = (const float4*)(g_h2 + ((size_t)p * EE + base) * MIDC);
        float4* d4 = (float4*)(h2s + p * 6144);
        for (int idx = t; idx < 1536; idx += 256) d4[idx] = s4[idx];
    }
    __syncthreads();

    // ---- phase 0b: t10m, s11m, denom ----
    if (t == 0) { float s = 0.f; for (int j = 0; j < 48; ++j) s += mskf[j]; dnm[0] = s; }
    for (int idx = t; idx < 768; idx += 256) {
        const int j = idx >> 4, i = idx & 15;
        const float* u = b10 + (base + j) * 3;
        const float* xr = xg1s + j * 48 + i * 3;
        t10m[idx] = mskf[j] * (u[0] * xr[0] + u[1] * xr[1] + u[2] * xr[2]);
    }
    for (int idx = t; idx < 6912; idx += 256) {
        const int i = idx & 15, j = (idx >> 4) % 48, fa = idx / 768;
        const int a = fa / 3, fi = fa - a * 3;
        const float* w = b11 + (base + j) * 27 + a * 9 + fi;
        const float* xr = xg1s + j * 48 + i * 3;
        s11m[idx] = mskf[j] * (w[0] * xr[0] + w[3] * xr[1] + w[6] * xr[2]);
    }
    __syncthreads();

    // ---- pair (0,0): h2[0] @ w3_00, contract with c00*xg0m -> acc0 ----
    gemm256(w3_00, b3_00, h2s + 0 * 6144, Rbuf, t);
    __syncthreads();
    {
        const int o = t >> 4, jg = t & 15;
        float part = 0.f;
        #pragma unroll
        for (int jj = 0; jj < 3; ++jj) {
            const int j = jg * 3 + jj;
            const float* rr = Rbuf + j * NPAD + o * 16;
            const float* xv = xg0m + j * 16;
            float q = 0.f;
            #pragma unroll
            for (int i = 0; i < 16; ++i) q = fmaf(rr[i], xv[i], q);
            part = fmaf(c00s[j], q, part);
        }
        atomicAdd(&acc0[o], part);
    }
    __syncthreads();

    // ---- pair (0,1): h2[1] @ w3_01, contract with xg0m, scale by v01 -> acc1 ----
    gemm256(w3_01, b3_01, h2s + 1 * 6144, Rbuf, t);
    __syncthreads();
    {
        const int o = t >> 4, jg = t & 15;
        float pa0 = 0.f, pa1 = 0.f, pa2 = 0.f;
        #pragma unroll
        for (int jj = 0; jj < 3; ++jj) {
            const int j = jg * 3 + jj;
            const float* rr = Rbuf + j * NPAD + o * 16;
            const float* xv = xg0m + j * 16;
            float q = 0.f;
            #pragma unroll
            for (int i = 0; i < 16; ++i) q = fmaf(rr[i], xv[i], q);
            pa0 = fmaf(v01s[j * 3 + 0], q, pa0);
            pa1 = fmaf(v01s[j * 3 + 1], q, pa1);
            pa2 = fmaf(v01s[j * 3 + 2], q, pa2);
        }
        atomicAdd(&acc1[o * 3 + 0], pa0);
        atomicAdd(&acc1[o * 3 + 1], pa1);
        atomicAdd(&acc1[o * 3 + 2], pa2);
    }
    __syncthreads();

    // ---- pair (1,0): h2[2] @ w3_10, contract with t10m -> acc0 ----
    gemm256(w3_10, b3_10, h2s + 2 * 6144, Rbuf, t);
    __syncthreads();
    {
        const int o = t >> 4, jg = t & 15;
        float part = 0.f;
        #pragma unroll
        for (int jj = 0; jj < 3; ++jj) {
            const int j = jg * 3 + jj;
            const float* rr = Rbuf + j * NPAD + o * 16;
            const float* tv = t10m + j * 16;
            float q = 0.f;
            #pragma unroll
            for (int i = 0; i < 16; ++i) q = fmaf(rr[i], tv[i], q);
            part += q;
        }
        atomicAdd(&acc0[o], part);
    }
    __syncthreads();

    // ---- pair (1,1): 4 chunks of 4 output-o's (192 cols each) ----
    for (int co = 0; co < 4; ++co) {
        gemm192(w3_11 + co * 192, b3_11 + co * 192, h2s + 3 * 6144, Rbuf, t);
        __syncthreads();
        if (t < 192) {
            const int jg = t / 12, rem = t % 12, ol = rem & 3, a = rem >> 2;
            float part = 0.f;
            #pragma unroll
            for (int jj = 0; jj < 3; ++jj) {
                const int j = jg * 3 + jj;
                const float* rr = Rbuf + j * NPAD + ol * 48;
                #pragma unroll
                for (int fi = 0; fi < 3; ++fi) {
                    const float* sv = s11m + (a * 3 + fi) * 768 + j * 16;
                    #pragma unroll
                    for (int i = 0; i < 16; ++i)
                        part = fmaf(rr[i * 3 + fi], sv[i], part);
                }
            }
            atomicAdd(&acc1[(co * 4 + ol) * 3 + a], part);
        }
        __syncthreads();
    }

    // ---- finalize: masked mean + self-interaction ----
    if (t < 64) {
        const int o = t >> 2, d = t & 3;
        const float dn = dnm[0];
        float r;
        if (d == 0) {
            r = acc0[o] / dn;
            #pragma unroll
            for (int i = 0; i < 16; ++i) r = fmaf(ks0[o * 16 + i], x0[n * 16 + i], r);
        } else {
            const int a = d - 1;
            r = acc1[o * 3 + a] / dn;
            #pragma unroll
            for (int i = 0; i < 16; ++i) r = fmaf(ks1[o * 16 + i], x1[(n * 16 + i) * 3 + a], r);
        }
        out[(n * 16 + o) * 4 + d] = r;
    }
}

// ---------------- launch ----------------
extern "C" void kernel_launch(void* const* d_in, const int* in_sizes, int n_in,
                              void* d_out, int out_size)
{
    const float* x0    = (const float*)d_in[0];
    const float* x1    = (const float*)d_in[1];
    const float* rel   = (const float*)d_in[2];
    const int*   nidx  = (const int*)d_in[3];
    const void*  maskp = d_in[4];
    const float* b00   = (const float*)d_in[5];
    const float* b01   = (const float*)d_in[6];
    const float* b10   = (const float*)d_in[7];
    const float* b11   = (const float*)d_in[8];
    const float* w1    = (const float*)d_in[9];
    const float* b1    = (const float*)d_in[10];
    const float* g1    = (const float*)d_in[11];
    const float* be1   = (const float*)d_in[12];
    const float* w2    = (const float*)d_in[13];
    const float* b2    = (const float*)d_in[14];
    const float* g2    = (const float*)d_in[15];
    const float* be2   = (const float*)d_in[16];
    const float* w3_00 = (const float*)d_in[17];
    const float* b3_00 = (const float*)d_in[18];
    const float* w3_01 = (const float*)d_in[19];
    const float* b3_01 = (const float*)d_in[20];
    const float* w3_10 = (const float*)d_in[21];
    const float* b3_10 = (const float*)d_in[22];
    const float* w3_11 = (const float*)d_in[23];
    const float* b3_11 = (const float*)d_in[24];
    const float* ks0   = (const float*)d_in[25];
    const float* ks1   = (const float*)d_in[26];
    float* out = (float*)d_out;

    const int smemBytes = K2_SMEM_FLOATS * 4;
    cudaFuncSetAttribute(k2_conv, cudaFuncAttributeMaxDynamicSharedMemorySize, smemBytes);

    k0_detect<<<1, 256>>>((const unsigned char*)maskp);
    k1_mlp<<<EE / 32, 256>>>(rel, w1, b1, g1, be1, w2, b2, g2, be2);
    k2_conv<<<NN, 256, smemBytes>>>(x0, x1, nidx, maskp,
                                    b00, b01, b10, b11,
                                    w3_00, b3_00, w3_01, b3_01,
                                    w3_10, b3_10, w3_11, b3_11,
                                    ks0, ks1, out);
}

// round 5
// speedup vs baseline: 1.5916x; 1.5916x over previous
#include <cuda_runtime.h>
#include <cstdint>

#define NN   512
#define JJ   48
#define EE   (NN*JJ)
#define MIDC 128
#define EPSL 1e-5f

// ---------------- device scratch ----------------
__device__ int g_mask_mode;                         // 0 = 1-byte bool, 1 = float32, 2 = int32
__device__ __align__(16) float g_h2[(size_t)4 * EE * MIDC];   // ~50 MB
__device__ __align__(16) float g_P[(size_t)NN * MIDC * 224];  // ~59 MB
__device__ __align__(16) float g_S[NN * 224];
__device__ float g_den[NN];

// ---------------- K0: mask dtype detection (small sample, statistically certain) ----
__global__ void k0_detect(const unsigned char* __restrict__ mb) {
    __shared__ int c1, c3;
    if (threadIdx.x == 0) { c1 = 0; c3 = 0; }
    __syncthreads();
    int l1 = 0, l3 = 0;
    // sample 2048 elements (8192 bytes valid for all dtypes)
    for (int i = threadIdx.x * 4; i < 8192; i += 1024) {
        if (mb[i + 1]) l1++;              // nonzero -> 1-byte bool data
        if (mb[i + 3] == 0x3Fu) l3++;     // top byte of float 1.0f
    }
    if (l1) atomicAdd(&c1, l1);
    if (l3) atomicAdd(&c3, l3);
    __syncthreads();
    if (threadIdx.x == 0) g_mask_mode = c1 ? 0 : (c3 ? 1 : 2);
}

// ---------------- K1: per-edge radial MLP (w1->LN->relu->w2->LN->relu) [R0, verified] ----
__global__ __launch_bounds__(256) void k1_mlp(
    const float* __restrict__ rel,
    const float* __restrict__ w1, const float* __restrict__ b1,
    const float* __restrict__ g1, const float* __restrict__ be1,
    const float* __restrict__ w2, const float* __restrict__ b2,
    const float* __restrict__ g2, const float* __restrict__ be2)
{
    __shared__ float h1s[32][MIDC];
    const int t = threadIdx.x, lane = t & 31, wp = t >> 5;
    const int e0 = blockIdx.x * 32;
    const int cg = t & 31, rg = t >> 5;

    for (int p = 0; p < 4; ++p) {
        const float* w1p = w1 + p * MIDC;  const float* b1p = b1 + p * MIDC;
        const float* g1p = g1 + p * MIDC;  const float* be1p = be1 + p * MIDC;

        #pragma unroll
        for (int q = 0; q < 4; ++q) {
            const int le = wp * 4 + q;
            const float d = rel[e0 + le];
            float a[4];
            #pragma unroll
            for (int s_ = 0; s_ < 4; ++s_) {
                int c = lane + 32 * s_;
                a[s_] = fmaf(d, w1p[c], b1p[c]);
            }
            float s = a[0] + a[1] + a[2] + a[3];
            float s2 = a[0]*a[0] + a[1]*a[1] + a[2]*a[2] + a[3]*a[3];
            #pragma unroll
            for (int off = 16; off; off >>= 1) {
                s  += __shfl_xor_sync(0xffffffffu, s,  off);
                s2 += __shfl_xor_sync(0xffffffffu, s2, off);
            }
            const float mu  = s * 0.0078125f;
            const float inv = rsqrtf(fmaf(-mu, mu, s2 * 0.0078125f) + EPSL);
            #pragma unroll
            for (int s_ = 0; s_ < 4; ++s_) {
                int c = lane + 32 * s_;
                h1s[le][c] = fmaxf(fmaf((a[s_] - mu) * inv, g1p[c], be1p[c]), 0.f);
            }
        }
        __syncwarp();

        float acc[4][4];
        #pragma unroll
        for (int q = 0; q < 4; ++q)
            acc[q][0] = acc[q][1] = acc[q][2] = acc[q][3] = 0.f;
        const float4* w2p = (const float4*)(w2 + p * MIDC * MIDC);
        #pragma unroll 4
        for (int k = 0; k < MIDC; ++k) {
            float4 wv = w2p[k * 32 + cg];
            #pragma unroll
            for (int q = 0; q < 4; ++q) {
                float av = h1s[rg * 4 + q][k];
                acc[q][0] = fmaf(av, wv.x, acc[q][0]);
                acc[q][1] = fmaf(av, wv.y, acc[q][1]);
                acc[q][2] = fmaf(av, wv.z, acc[q][2]);
                acc[q][3] = fmaf(av, wv.w, acc[q][3]);
            }
        }
        const float4 b2v  = ((const float4*)(b2  + p * MIDC))[cg];
        const float4 g2v  = ((const float4*)(g2  + p * MIDC))[cg];
        const float4 be2v = ((const float4*)(be2 + p * MIDC))[cg];
        #pragma unroll
        for (int q = 0; q < 4; ++q) {
            float v0 = acc[q][0] + b2v.x, v1 = acc[q][1] + b2v.y;
            float v2 = acc[q][2] + b2v.z, v3 = acc[q][3] + b2v.w;
            float s  = v0 + v1 + v2 + v3;
            float s2 = v0*v0 + v1*v1 + v2*v2 + v3*v3;
            #pragma unroll
            for (int off = 16; off; off >>= 1) {
                s  += __shfl_xor_sync(0xffffffffu, s,  off);
                s2 += __shfl_xor_sync(0xffffffffu, s2, off);
            }
            const float mu  = s * 0.0078125f;
            const float inv = rsqrtf(fmaf(-mu, mu, s2 * 0.0078125f) + EPSL);
            float4 o;
            o.x = fmaxf(fmaf((v0 - mu) * inv, g2v.x, be2v.x), 0.f);
            o.y = fmaxf(fmaf((v1 - mu) * inv, g2v.y, be2v.y), 0.f);
            o.z = fmaxf(fmaf((v2 - mu) * inv, g2v.z, be2v.z), 0.f);
            o.w = fmaxf(fmaf((v3 - mu) * inv, g2v.w, be2v.w), 0.f);
            ((float4*)(g_h2 + ((size_t)p * EE + e0 + rg * 4 + q) * MIDC))[cg] = o;
        }
        __syncwarp();
    }
}

// ---------------- kP: per-(node,pair) P = h2^T @ s, plus S sums + denom ----------------
template<int D>
__device__ __forceinline__ void pgemm(const float* __restrict__ h2s,
                                      const float* __restrict__ sArr,
                                      float* __restrict__ Pout, int t)
{
    constexpr int DPT = D / 8;
    const int mid0 = (t & 31) * 4, d0 = (t >> 5) * DPT;
    float acc[4][DPT];
    #pragma unroll
    for (int m = 0; m < 4; ++m)
        #pragma unroll
        for (int d = 0; d < DPT; ++d) acc[m][d] = 0.f;

    #pragma unroll 2
    for (int j = 0; j < JJ; ++j) {
        const float4 hv = *(const float4*)(h2s + j * MIDC + mid0);
        float sv[DPT];
        #pragma unroll
        for (int d = 0; d < DPT; ++d) sv[d] = sArr[j * D + d0 + d];
        #pragma unroll
        for (int d = 0; d < DPT; ++d) {
            acc[0][d] = fmaf(hv.x, sv[d], acc[0][d]);
            acc[1][d] = fmaf(hv.y, sv[d], acc[1][d]);
            acc[2][d] = fmaf(hv.z, sv[d], acc[2][d]);
            acc[3][d] = fmaf(hv.w, sv[d], acc[3][d]);
        }
    }
    #pragma unroll
    for (int m = 0; m < 4; ++m)
        #pragma unroll
        for (int d = 0; d < DPT; ++d)
            Pout[(size_t)(mid0 + m) * 224 + d0 + d] = acc[m][d];
}

// dyn smem floats: h2s[48][128] @0 (6144) | sArr[48][<=144] @6144 (6912) |
//                  xg @13056 (2304) | mskf @15360 (48)  -> 15408 floats
#define KP_SMEM_FLOATS 15424

__global__ __launch_bounds__(256) void k_P(
    const float* __restrict__ x0, const float* __restrict__ x1,
    const int* __restrict__ nidx, const void* __restrict__ maskp,
    const float* __restrict__ b00, const float* __restrict__ b01,
    const float* __restrict__ b10, const float* __restrict__ b11)
{
    extern __shared__ float sm[];
    float* h2s  = sm;
    float* sArr = sm + 6144;
    float* xg   = sm + 13056;
    float* mskf = sm + 15360;

    const int n = blockIdx.x, p = blockIdx.y, t = threadIdx.x;
    const int base = n * JJ;

    { // h2 slice (48 rows x 128) — contiguous copy
        const float4* src = (const float4*)(g_h2 + ((size_t)p * EE + base) * MIDC);
        float4* dst = (float4*)h2s;
        #pragma unroll
        for (int i = t; i < 1536; i += 256) dst[i] = src[i];
    }
    if (t < 48) {
        const int j = t;
        const int mode = g_mask_mode;
        float mf;
        if (mode == 0)      mf = ((const unsigned char*)maskp)[base + j] ? 1.f : 0.f;
        else if (mode == 1) mf = (((const float*)maskp)[base + j] != 0.f) ? 1.f : 0.f;
        else                mf = ((const int*)maskp)[base + j] ? 1.f : 0.f;
        mskf[j] = mf;
        const int nb = nidx[base + j];
        if (p < 2) {
            #pragma unroll
            for (int i = 0; i < 16; ++i) xg[j * 16 + i] = mf * x0[nb * 16 + i];
        } else {
            #pragma unroll
            for (int i = 0; i < 48; ++i) xg[j * 48 + i] = x1[nb * 48 + i];
        }
    }
    __syncthreads();

    if (p == 0) {
        for (int idx = t; idx < 48 * 16; idx += 256) {
            const int j = idx >> 4, i = idx & 15;
            sArr[idx] = b00[base + j] * xg[j * 16 + i];
        }
    } else if (p == 1) {
        for (int idx = t; idx < 48 * 48; idx += 256) {
            const int j = idx / 48, d = idx % 48, u = d >> 4, i = d & 15;
            sArr[j * 48 + d] = b01[(base + j) * 3 + u] * xg[j * 16 + i];
        }
    } else if (p == 2) {
        for (int idx = t; idx < 48 * 16; idx += 256) {
            const int j = idx >> 4, i = idx & 15;
            const float* u = b10 + (base + j) * 3;
            const float* xr = xg + j * 48 + i * 3;
            sArr[idx] = mskf[j] * (u[0] * xr[0] + u[1] * xr[1] + u[2] * xr[2]);
        }
    } else {
        for (int idx = t; idx < 48 * 144; idx += 256) {
            const int j = idx / 144, d = idx % 144;
            const int a = d / 48, r = d % 48, i = r / 3, f = r % 3;
            const float* w = b11 + (base + j) * 27 + a * 9 + f;
            const float* xr = xg + j * 48 + i * 3;
            sArr[j * 144 + d] = mskf[j] * (w[0] * xr[0] + w[3] * xr[1] + w[6] * xr[2]);
        }
    }
    __syncthreads();

    if (p == 0 && t == 0) {
        float s = 0.f;
        for (int j = 0; j < 48; ++j) s += mskf[j];
        g_den[n] = s;
    }
    const int D = (p == 0) ? 16 : (p == 1) ? 48 : (p == 2) ? 16 : 144;
    const int off = (p == 0) ? 0 : (p == 1) ? 16 : (p == 2) ? 64 : 80;
    for (int d = t; d < D; d += 256) {
        float s = 0.f;
        for (int j = 0; j < 48; ++j) s += sArr[j * D + d];
        g_S[n * 224 + off + d] = s;
    }

    float* Pout = g_P + (size_t)n * MIDC * 224 + off;
    if (p == 0)      pgemm<16>(h2s, sArr, Pout, t);
    else if (p == 1) pgemm<48>(h2s, sArr, Pout, t);
    else if (p == 2) pgemm<16>(h2s, sArr, Pout, t);
    else             pgemm<144>(h2s, sArr, Pout, t);
}

// ---------------- kF: final contraction out = w3 . P  (+bias via S, mean, self) -------
// dyn smem floats: w3s[16][1536] @0 (24576) | Ps[4][16][224] @24576 (14336) -> 38912
#define KF_SMEM_FLOATS 38912

__global__ __launch_bounds__(256) void k_F(
    const float* __restrict__ x0, const float* __restrict__ x1,
    const float* __restrict__ w300, const float* __restrict__ b300,
    const float* __restrict__ w301, const float* __restrict__ b301,
    const float* __restrict__ w310, const float* __restrict__ b310,
    const float* __restrict__ w311, const float* __restrict__ b311,
    const float* __restrict__ ks0, const float* __restrict__ ks1,
    float* __restrict__ out)
{
    extern __shared__ float sm[];
    float* w3s = sm;            // [mid16][1536]: 00@0, 01@256, 10@512, 11@768
    float* Ps  = sm + 24576;    // [q][16][224]

    const int t = threadIdx.x;
    const int q = t >> 6, w = t & 63, o = w >> 2, d = w & 3;
    const int n = blockIdx.x * 4 + q;
    float acc = 0.f;

    for (int mc = 0; mc < 8; ++mc) {
        __syncthreads();
        { // stage w3 chunk (16 mids)
            const float4* s00 = (const float4*)(w300 + mc * 16 * 256);
            const float4* s01 = (const float4*)(w301 + mc * 16 * 256);
            const float4* s10 = (const float4*)(w310 + mc * 16 * 256);
            for (int i = t; i < 1024; i += 256) {
                const int m = i >> 6, c = (i & 63) * 4;
                *(float4*)(w3s + m * 1536 + c)       = s00[i];
                *(float4*)(w3s + m * 1536 + 256 + c) = s01[i];
                *(float4*)(w3s + m * 1536 + 512 + c) = s10[i];
            }
            const float4* s11 = (const float4*)(w311 + mc * 16 * 768);
            for (int i = t; i < 3072; i += 256) {
                const int m = i / 192, c = (i % 192) * 4;
                *(float4*)(w3s + m * 1536 + 768 + c) = s11[i];
            }
            // stage P chunks for 4 nodes (contiguous 16x224)
            for (int qq = 0; qq < 4; ++qq) {
                const float4* sp = (const float4*)(g_P + ((size_t)(blockIdx.x * 4 + qq) * MIDC + mc * 16) * 224);
                float4* dp = (float4*)(Ps + qq * 3584);
                for (int i = t; i < 896; i += 256) dp[i] = sp[i];
            }
        }
        __syncthreads();

        #pragma unroll 1
        for (int m = 0; m < 16; ++m) {
            const float* wr = w3s + m * 1536;
            const float* pr = Ps + q * 3584 + m * 224;
            if (d == 0) {
                #pragma unroll
                for (int i = 0; i < 16; i += 4) {
                    const float4 wa = *(const float4*)(wr + o * 16 + i);
                    const float4 pa = *(const float4*)(pr + i);
                    const float4 wb = *(const float4*)(wr + 512 + o * 16 + i);
                    const float4 pb = *(const float4*)(pr + 64 + i);
                    acc = fmaf(wa.x, pa.x, acc); acc = fmaf(wa.y, pa.y, acc);
                    acc = fmaf(wa.z, pa.z, acc); acc = fmaf(wa.w, pa.w, acc);
                    acc = fmaf(wb.x, pb.x, acc); acc = fmaf(wb.y, pb.y, acc);
                    acc = fmaf(wb.z, pb.z, acc); acc = fmaf(wb.w, pb.w, acc);
                }
            } else {
                const int a = d - 1;
                #pragma unroll
                for (int i = 0; i < 16; i += 4) {
                    const float4 wa = *(const float4*)(wr + 256 + o * 16 + i);
                    const float4 pa = *(const float4*)(pr + 16 + a * 16 + i);
                    acc = fmaf(wa.x, pa.x, acc); acc = fmaf(wa.y, pa.y, acc);
                    acc = fmaf(wa.z, pa.z, acc); acc = fmaf(wa.w, pa.w, acc);
                }
                #pragma unroll
                for (int r = 0; r < 48; r += 4) {
                    const float4 wa = *(const float4*)(wr + 768 + o * 48 + r);
                    const float4 pa = *(const float4*)(pr + 80 + a * 48 + r);
                    acc = fmaf(wa.x, pa.x, acc); acc = fmaf(wa.y, pa.y, acc);
                    acc = fmaf(wa.z, pa.z, acc); acc = fmaf(wa.w, pa.w, acc);
                }
            }
        }
    }

    // bias via S, masked mean, self-interaction
    const float dn = g_den[n];
    const float* Sv = g_S + n * 224;
    if (d == 0) {
        #pragma unroll
        for (int i = 0; i < 16; ++i) {
            acc = fmaf(b300[o * 16 + i], Sv[i], acc);
            acc = fmaf(b310[o * 16 + i], Sv[64 + i], acc);
        }
        acc /= dn;
        #pragma unroll
        for (int i = 0; i < 16; ++i) acc = fmaf(ks0[o * 16 + i], x0[n * 16 + i], acc);
    } else {
        const int a = d - 1;
        #pragma unroll
        for (int i = 0; i < 16; ++i) acc = fmaf(b301[o * 16 + i], Sv[16 + a * 16 + i], acc);
        #pragma unroll
        for (int r = 0; r < 48; ++r) acc = fmaf(b311[o * 48 + r], Sv[80 + a * 48 + r], acc);
        acc /= dn;
        #pragma unroll
        for (int i = 0; i < 16; ++i) acc = fmaf(ks1[o * 16 + i], x1[(n * 16 + i) * 3 + a], acc);
    }
    out[(n * 16 + o) * 4 + d] = acc;
}

// ---------------- launch ----------------
extern "C" void kernel_launch(void* const* d_in, const int* in_sizes, int n_in,
                              void* d_out, int out_size)
{
    const float* x0    = (const float*)d_in[0];
    const float* x1    = (const float*)d_in[1];
    const float* rel   = (const float*)d_in[2];
    const int*   nidx  = (const int*)d_in[3];
    const void*  maskp = d_in[4];
    const float* b00   = (const float*)d_in[5];
    const float* b01   = (const float*)d_in[6];
    const float* b10   = (const float*)d_in[7];
    const float* b11   = (const float*)d_in[8];
    const float* w1    = (const float*)d_in[9];
    const float* b1    = (const float*)d_in[10];
    const float* g1    = (const float*)d_in[11];
    const float* be1   = (const float*)d_in[12];
    const float* w2    = (const float*)d_in[13];
    const float* b2    = (const float*)d_in[14];
    const float* g2    = (const float*)d_in[15];
    const float* be2   = (const float*)d_in[16];
    const float* w3_00 = (const float*)d_in[17];
    const float* b3_00 = (const float*)d_in[18];
    const float* w3_01 = (const float*)d_in[19];
    const float* b3_01 = (const float*)d_in[20];
    const float* w3_10 = (const float*)d_in[21];
    const float* b3_10 = (const float*)d_in[22];
    const float* w3_11 = (const float*)d_in[23];
    const float* b3_11 = (const float*)d_in[24];
    const float* ks0   = (const float*)d_in[25];
    const float* ks1   = (const float*)d_in[26];
    float* out = (float*)d_out;

    const int smP = KP_SMEM_FLOATS * 4;
    const int smF = KF_SMEM_FLOATS * 4;
    cudaFuncSetAttribute(k_P, cudaFuncAttributeMaxDynamicSharedMemorySize, smP);
    cudaFuncSetAttribute(k_F, cudaFuncAttributeMaxDynamicSharedMemorySize, smF);

    k0_detect<<<1, 256>>>((const unsigned char*)maskp);
    k1_mlp<<<EE / 32, 256>>>(rel, w1, b1, g1, be1, w2, b2, g2, be2);
    k_P<<<dim3(NN, 4), 256, smP>>>(x0, x1, nidx, maskp, b00, b01, b10, b11);
    k_F<<<NN / 4, 256, smF>>>(x0, x1, w3_00, b3_00, w3_01, b3_01,
                              w3_10, b3_10, w3_11, b3_11, ks0, ks1, out);
}

// round 11
// speedup vs baseline: 2.2408x; 1.4079x over previous
#include <cuda_runtime.h>
#include <cstdint>

#define NN   512
#define JJ   48
#define EE   (NN*JJ)
#define MIDC 128
#define EPSL 1e-5f

// ---------------- device scratch ----------------
__device__ int g_mask_mode;                         // 0 = 1-byte bool, 1 = float32, 2 = int32
__device__ __align__(16) float g_h2[(size_t)4 * EE * MIDC];   // ~50 MB
__device__ __align__(16) float g_P[(size_t)NN * MIDC * 224];  // ~59 MB
__device__ __align__(16) float g_S[NN * 224];
__device__ float g_den[NN];
__device__ __align__(16) float g_part[16 * NN * 64];          // per-mid-chunk partials (2 MB)

// ---------------- K0: mask dtype detection ----------------
__global__ void k0_detect(const unsigned char* __restrict__ mb) {
    __shared__ int c1, c3;
    if (threadIdx.x == 0) { c1 = 0; c3 = 0; }
    __syncthreads();
    int l1 = 0, l3 = 0;
    for (int i = threadIdx.x * 4; i < 8192; i += 1024) {
        if (mb[i + 1]) l1++;
        if (mb[i + 3] == 0x3Fu) l3++;
    }
    if (l1) atomicAdd(&c1, l1);
    if (l3) atomicAdd(&c3, l3);
    __syncthreads();
    if (threadIdx.x == 0) g_mask_mode = c1 ? 0 : (c3 ? 1 : 2);
}

// ---------------- K1: per-edge radial MLP (verified) ----------------
__global__ __launch_bounds__(256) void k1_mlp(
    const float* __restrict__ rel,
    const float* __restrict__ w1, const float* __restrict__ b1,
    const float* __restrict__ g1, const float* __restrict__ be1,
    const float* __restrict__ w2, const float* __restrict__ b2,
    const float* __restrict__ g2, const float* __restrict__ be2)
{
    __shared__ float h1s[32][MIDC];
    const int t = threadIdx.x, lane = t & 31, wp = t >> 5;
    const int e0 = blockIdx.x * 32;
    const int cg = t & 31, rg = t >> 5;

    for (int p = 0; p < 4; ++p) {
        const float* w1p = w1 + p * MIDC;  const float* b1p = b1 + p * MIDC;
        const float* g1p = g1 + p * MIDC;  const float* be1p = be1 + p * MIDC;

        #pragma unroll
        for (int q = 0; q < 4; ++q) {
            const int le = wp * 4 + q;
            const float d = rel[e0 + le];
            float a[4];
            #pragma unroll
            for (int s_ = 0; s_ < 4; ++s_) {
                int c = lane + 32 * s_;
                a[s_] = fmaf(d, w1p[c], b1p[c]);
            }
            float s = a[0] + a[1] + a[2] + a[3];
            float s2 = a[0]*a[0] + a[1]*a[1] + a[2]*a[2] + a[3]*a[3];
            #pragma unroll
            for (int off = 16; off; off >>= 1) {
                s  += __shfl_xor_sync(0xffffffffu, s,  off);
                s2 += __shfl_xor_sync(0xffffffffu, s2, off);
            }
            const float mu  = s * 0.0078125f;
            const float inv = rsqrtf(fmaf(-mu, mu, s2 * 0.0078125f) + EPSL);
            #pragma unroll
            for (int s_ = 0; s_ < 4; ++s_) {
                int c = lane + 32 * s_;
                h1s[le][c] = fmaxf(fmaf((a[s_] - mu) * inv, g1p[c], be1p[c]), 0.f);
            }
        }
        __syncwarp();

        float acc[4][4];
        #pragma unroll
        for (int q = 0; q < 4; ++q)
            acc[q][0] = acc[q][1] = acc[q][2] = acc[q][3] = 0.f;
        const float4* w2p = (const float4*)(w2 + p * MIDC * MIDC);
        #pragma unroll 4
        for (int k = 0; k < MIDC; ++k) {
            float4 wv = w2p[k * 32 + cg];
            #pragma unroll
            for (int q = 0; q < 4; ++q) {
                float av = h1s[rg * 4 + q][k];
                acc[q][0] = fmaf(av, wv.x, acc[q][0]);
                acc[q][1] = fmaf(av, wv.y, acc[q][1]);
                acc[q][2] = fmaf(av, wv.z, acc[q][2]);
                acc[q][3] = fmaf(av, wv.w, acc[q][3]);
            }
        }
        const float4 b2v  = ((const float4*)(b2  + p * MIDC))[cg];
        const float4 g2v  = ((const float4*)(g2  + p * MIDC))[cg];
        const float4 be2v = ((const float4*)(be2 + p * MIDC))[cg];
        #pragma unroll
        for (int q = 0; q < 4; ++q) {
            float v0 = acc[q][0] + b2v.x, v1 = acc[q][1] + b2v.y;
            float v2 = acc[q][2] + b2v.z, v3 = acc[q][3] + b2v.w;
            float s  = v0 + v1 + v2 + v3;
            float s2 = v0*v0 + v1*v1 + v2*v2 + v3*v3;
            #pragma unroll
            for (int off = 16; off; off >>= 1) {
                s  += __shfl_xor_sync(0xffffffffu, s,  off);
                s2 += __shfl_xor_sync(0xffffffffu, s2, off);
            }
            const float mu  = s * 0.0078125f;
            const float inv = rsqrtf(fmaf(-mu, mu, s2 * 0.0078125f) + EPSL);
            float4 o;
            o.x = fmaxf(fmaf((v0 - mu) * inv, g2v.x, be2v.x), 0.f);
            o.y = fmaxf(fmaf((v1 - mu) * inv, g2v.y, be2v.y), 0.f);
            o.z = fmaxf(fmaf((v2 - mu) * inv, g2v.z, be2v.z), 0.f);
            o.w = fmaxf(fmaf((v3 - mu) * inv, g2v.w, be2v.w), 0.f);
            ((float4*)(g_h2 + ((size_t)p * EE + e0 + rg * 4 + q) * MIDC))[cg] = o;
        }
        __syncwarp();
    }
}

// ---------------- kP: per-(node,pair) P = h2^T @ s, plus S sums + denom ----------------
template<int D>
__device__ __forceinline__ void pgemm(const float* __restrict__ h2s,
                                      const float* __restrict__ sArr,
                                      float* __restrict__ Pout, int t)
{
    constexpr int DPT = D / 8;
    const int mid0 = (t & 31) * 4, d0 = (t >> 5) * DPT;
    float acc[4][DPT];
    #pragma unroll
    for (int m = 0; m < 4; ++m)
        #pragma unroll
        for (int d = 0; d < DPT; ++d) acc[m][d] = 0.f;

    #pragma unroll 2
    for (int j = 0; j < JJ; ++j) {
        const float4 hv = *(const float4*)(h2s + j * MIDC + mid0);
        float sv[DPT];
        #pragma unroll
        for (int d = 0; d < DPT; ++d) sv[d] = sArr[j * D + d0 + d];
        #pragma unroll
        for (int d = 0; d < DPT; ++d) {
            acc[0][d] = fmaf(hv.x, sv[d], acc[0][d]);
            acc[1][d] = fmaf(hv.y, sv[d], acc[1][d]);
            acc[2][d] = fmaf(hv.z, sv[d], acc[2][d]);
            acc[3][d] = fmaf(hv.w, sv[d], acc[3][d]);
        }
    }
    #pragma unroll
    for (int m = 0; m < 4; ++m)
        #pragma unroll
        for (int d = 0; d < DPT; ++d)
            Pout[(size_t)(mid0 + m) * 224 + d0 + d] = acc[m][d];
}

#define KP_SMEM_FLOATS 15424

__global__ __launch_bounds__(256) void k_P(
    const float* __restrict__ x0, const float* __restrict__ x1,
    const int* __restrict__ nidx, const void* __restrict__ maskp,
    const float* __restrict__ b00, const float* __restrict__ b01,
    const float* __restrict__ b10, const float* __restrict__ b11)
{
    extern __shared__ float sm[];
    float* h2s  = sm;
    float* sArr = sm + 6144;
    float* xg   = sm + 13056;
    float* mskf = sm + 15360;

    const int n = blockIdx.x, p = blockIdx.y, t = threadIdx.x;
    const int base = n * JJ;

    {
        const float4* src = (const float4*)(g_h2 + ((size_t)p * EE + base) * MIDC);
        float4* dst = (float4*)h2s;
        #pragma unroll
        for (int i = t; i < 1536; i += 256) dst[i] = src[i];
    }
    if (t < 48) {
        const int j = t;
        const int mode = g_mask_mode;
        float mf;
        if (mode == 0)      mf = ((const unsigned char*)maskp)[base + j] ? 1.f : 0.f;
        else if (mode == 1) mf = (((const float*)maskp)[base + j] != 0.f) ? 1.f : 0.f;
        else                mf = ((const int*)maskp)[base + j] ? 1.f : 0.f;
        mskf[j] = mf;
        const int nb = nidx[base + j];
        if (p < 2) {
            #pragma unroll
            for (int i = 0; i < 16; ++i) xg[j * 16 + i] = mf * x0[nb * 16 + i];
        } else {
            #pragma unroll
            for (int i = 0; i < 48; ++i) xg[j * 48 + i] = x1[nb * 48 + i];
        }
    }
    __syncthreads();

    if (p == 0) {
        for (int idx = t; idx < 48 * 16; idx += 256) {
            const int j = idx >> 4, i = idx & 15;
            sArr[idx] = b00[base + j] * xg[j * 16 + i];
        }
    } else if (p == 1) {
        for (int idx = t; idx < 48 * 48; idx += 256) {
            const int j = idx / 48, d = idx % 48, u = d >> 4, i = d & 15;
            sArr[j * 48 + d] = b01[(base + j) * 3 + u] * xg[j * 16 + i];
        }
    } else if (p == 2) {
        for (int idx = t; idx < 48 * 16; idx += 256) {
            const int j = idx >> 4, i = idx & 15;
            const float* u = b10 + (base + j) * 3;
            const float* xr = xg + j * 48 + i * 3;
            sArr[idx] = mskf[j] * (u[0] * xr[0] + u[1] * xr[1] + u[2] * xr[2]);
        }
    } else {
        for (int idx = t; idx < 48 * 144; idx += 256) {
            const int j = idx / 144, d = idx % 144;
            const int a = d / 48, r = d % 48, i = r / 3, f = r % 3;
            const float* w = b11 + (base + j) * 27 + a * 9 + f;
            const float* xr = xg + j * 48 + i * 3;
            sArr[j * 144 + d] = mskf[j] * (w[0] * xr[0] + w[3] * xr[1] + w[6] * xr[2]);
        }
    }
    __syncthreads();

    if (p == 0 && t == 0) {
        float s = 0.f;
        for (int j = 0; j < 48; ++j) s += mskf[j];
        g_den[n] = s;
    }
    const int D = (p == 0) ? 16 : (p == 1) ? 48 : (p == 2) ? 16 : 144;
    const int off = (p == 0) ? 0 : (p == 1) ? 16 : (p == 2) ? 64 : 80;
    for (int d = t; d < D; d += 256) {
        float s = 0.f;
        for (int j = 0; j < 48; ++j) s += sArr[j * D + d];
        g_S[n * 224 + off + d] = s;
    }

    float* Pout = g_P + (size_t)n * MIDC * 224 + off;
    if (p == 0)      pgemm<16>(h2s, sArr, Pout, t);
    else if (p == 1) pgemm<48>(h2s, sArr, Pout, t);
    else if (p == 2) pgemm<16>(h2s, sArr, Pout, t);
    else             pgemm<144>(h2s, sArr, Pout, t);
}

// ---------------- k_F2: tiled contraction out_part = w3 . P ----------------
// grid (32 node-tiles, 16 mid-chunks of 8); 256 thr = 16 nodes x 16 o.
// smem floats: Ps[16n][8m][224] @0 (28672) | w00s[8][16][20] @28672 (2560)
//              w01s @31232 (2560) | w10s @33792 (2560) | w11s[8][16][60] @36352 (7680)
#define KF2_SMEM_FLOATS 44032

__device__ __forceinline__ float dot16r(const float* __restrict__ r, const float* __restrict__ p) {
    float a = 0.f;
    #pragma unroll
    for (int i = 0; i < 16; i += 4) {
        const float4 pv = *(const float4*)(p + i);
        a = fmaf(r[i],     pv.x, a); a = fmaf(r[i + 1], pv.y, a);
        a = fmaf(r[i + 2], pv.z, a); a = fmaf(r[i + 3], pv.w, a);
    }
    return a;
}
__device__ __forceinline__ float dot48r(const float* __restrict__ r, const float* __restrict__ p) {
    float a = 0.f;
    #pragma unroll
    for (int i = 0; i < 48; i += 4) {
        const float4 pv = *(const float4*)(p + i);
        a = fmaf(r[i],     pv.x, a); a = fmaf(r[i + 1], pv.y, a);
        a = fmaf(r[i + 2], pv.z, a); a = fmaf(r[i + 3], pv.w, a);
    }
    return a;
}

__global__ __launch_bounds__(256) void k_F2(
    const float* __restrict__ w300, const float* __restrict__ w301,
    const float* __restrict__ w310, const float* __restrict__ w311)
{
    extern __shared__ float sm[];
    float* Ps   = sm;
    float* w00s = sm + 28672;
    float* w01s = sm + 31232;
    float* w10s = sm + 33792;
    float* w11s = sm + 36352;

    const int tile = blockIdx.x, mc = blockIdx.y, t = threadIdx.x;
    const int mid0 = mc * 8;

    // stage w3 chunks (padded rows: 20 / 60 floats to dodge bank conflicts)
    for (int i = t; i < 512; i += 256) {
        const int m = i >> 6, c = (i & 63) * 4;
        const int o = c >> 4, ii = c & 15;
        const float4 v0 = *(const float4*)(w300 + (mid0 + m) * 256 + c);
        const float4 v1 = *(const float4*)(w301 + (mid0 + m) * 256 + c);
        const float4 v2 = *(const float4*)(w310 + (mid0 + m) * 256 + c);
        *(float4*)(w00s + (m * 16 + o) * 20 + ii) = v0;
        *(float4*)(w01s + (m * 16 + o) * 20 + ii) = v1;
        *(float4*)(w10s + (m * 16 + o) * 20 + ii) = v2;
    }
    for (int i = t; i < 1536; i += 256) {
        const int m = i / 192, c = (i % 192) * 4;
        const int o = c / 48, r = c % 48;
        const float4 v = *(const float4*)(w311 + (mid0 + m) * 768 + c);
        *(float4*)(w11s + (m * 16 + o) * 60 + r) = v;
    }
    // stage P tile: 16 nodes x 8 mids x 224
    {
        const float* src = g_P + (size_t)(tile * 16) * 28672 + mid0 * 224;
        for (int i = t; i < 7168; i += 256) {
            const int nm = i / 56, c4 = (i % 56) * 4;
            const int n = nm >> 3, m = nm & 7;
            *(float4*)(Ps + nm * 224 + c4) =
                *(const float4*)(src + (size_t)n * 28672 + m * 224 + c4);
        }
    }
    __syncthreads();

    const int nl = t >> 4, o = t & 15;
    float a0 = 0.f, a1 = 0.f, a2 = 0.f, a3 = 0.f;

    #pragma unroll 1
    for (int m = 0; m < 8; ++m) {
        const float* P  = Ps + (nl * 8 + m) * 224;
        const float* W0 = w00s + (m * 16 + o) * 20;
        const float* W2 = w10s + (m * 16 + o) * 20;
        // degree-0 output: pairs (0,0) and (1,0)
        #pragma unroll
        for (int i = 0; i < 16; i += 4) {
            const float4 w0 = *(const float4*)(W0 + i);
            const float4 p0 = *(const float4*)(P + i);
            const float4 w2 = *(const float4*)(W2 + i);
            const float4 p2 = *(const float4*)(P + 64 + i);
            a0 = fmaf(w0.x, p0.x, a0); a0 = fmaf(w0.y, p0.y, a0);
            a0 = fmaf(w0.z, p0.z, a0); a0 = fmaf(w0.w, p0.w, a0);
            a0 = fmaf(w2.x, p2.x, a0); a0 = fmaf(w2.y, p2.y, a0);
            a0 = fmaf(w2.z, p2.z, a0); a0 = fmaf(w2.w, p2.w, a0);
        }
        // degree-1 outputs: pair (0,1), w fragment reused for 3 components
        {
            const float* W1 = w01s + (m * 16 + o) * 20;
            float r01[16];
            #pragma unroll
            for (int i = 0; i < 16; i += 4) *(float4*)(r01 + i) = *(const float4*)(W1 + i);
            a1 += dot16r(r01, P + 16);
            a2 += dot16r(r01, P + 32);
            a3 += dot16r(r01, P + 48);
        }
        // degree-1 outputs: pair (1,1)
        {
            const float* W3 = w11s + (m * 16 + o) * 60;
            float r11[48];
            #pragma unroll
            for (int i = 0; i < 48; i += 4) *(float4*)(r11 + i) = *(const float4*)(W3 + i);
            a1 += dot48r(r11, P + 80);
            a2 += dot48r(r11, P + 128);
            a3 += dot48r(r11, P + 176);
        }
    }

    float* dst = g_part + (size_t)mc * (NN * 64) + (size_t)(tile * 16 + nl) * 64 + o * 4;
    dst[0] = a0; dst[1] = a1; dst[2] = a2; dst[3] = a3;
}

// ---------------- k_E: reduce partials + bias via S + mean + self ----------------
__global__ __launch_bounds__(256) void k_E(
    const float* __restrict__ x0, const float* __restrict__ x1,
    const float* __restrict__ b300, const float* __restrict__ b301,
    const float* __restrict__ b310, const float* __restrict__ b311,
    const float* __restrict__ ks0, const float* __restrict__ ks1,
    float* __restrict__ out)
{
    const int gid = blockIdx.x * 256 + threadIdx.x;   // 32768 total
    const int n = gid >> 6, w = gid & 63, o = w >> 2, d = w & 3;

    float acc = 0.f;
    #pragma unroll
    for (int mcx = 0; mcx < 16; ++mcx) acc += g_part[mcx * (NN * 64) + gid];

    const float dn = g_den[n];
    const float* Sv = g_S + n * 224;
    if (d == 0) {
        #pragma unroll
        for (int i = 0; i < 16; ++i) {
            acc = fmaf(b300[o * 16 + i], Sv[i], acc);
            acc = fmaf(b310[o * 16 + i], Sv[64 + i], acc);
        }
        acc /= dn;
        #pragma unroll
        for (int i = 0; i < 16; ++i) acc = fmaf(ks0[o * 16 + i], x0[n * 16 + i], acc);
    } else {
        const int a = d - 1;
        #pragma unroll
        for (int i = 0; i < 16; ++i) acc = fmaf(b301[o * 16 + i], Sv[16 + a * 16 + i], acc);
        #pragma unroll
        for (int r = 0; r < 48; ++r) acc = fmaf(b311[o * 48 + r], Sv[80 + a * 48 + r], acc);
        acc /= dn;
        #pragma unroll
        for (int i = 0; i < 16; ++i) acc = fmaf(ks1[o * 16 + i], x1[(n * 16 + i) * 3 + a], acc);
    }
    out[gid] = acc;
}

// ---------------- launch ----------------
extern "C" void kernel_launch(void* const* d_in, const int* in_sizes, int n_in,
                              void* d_out, int out_size)
{
    const float* x0    = (const float*)d_in[0];
    const float* x1    = (const float*)d_in[1];
    const float* rel   = (const float*)d_in[2];
    const int*   nidx  = (const int*)d_in[3];
    const void*  maskp = d_in[4];
    const float* b00   = (const float*)d_in[5];
    const float* b01   = (const float*)d_in[6];
    const float* b10   = (const float*)d_in[7];
    const float* b11   = (const float*)d_in[8];
    const float* w1    = (const float*)d_in[9];
    const float* b1    = (const float*)d_in[10];
    const float* g1    = (const float*)d_in[11];
    const float* be1   = (const float*)d_in[12];
    const float* w2    = (const float*)d_in[13];
    const float* b2    = (const float*)d_in[14];
    const float* g2    = (const float*)d_in[15];
    const float* be2   = (const float*)d_in[16];
    const float* w3_00 = (const float*)d_in[17];
    const float* b3_00 = (const float*)d_in[18];
    const float* w3_01 = (const float*)d_in[19];
    const float* b3_01 = (const float*)d_in[20];
    const float* w3_10 = (const float*)d_in[21];
    const float* b3_10 = (const float*)d_in[22];
    const float* w3_11 = (const float*)d_in[23];
    const float* b3_11 = (const float*)d_in[24];
    const float* ks0   = (const float*)d_in[25];
    const float* ks1   = (const float*)d_in[26];
    float* out = (float*)d_out;

    const int smP  = KP_SMEM_FLOATS * 4;
    const int smF2 = KF2_SMEM_FLOATS * 4;
    cudaFuncSetAttribute(k_P,  cudaFuncAttributeMaxDynamicSharedMemorySize, smP);
    cudaFuncSetAttribute(k_F2, cudaFuncAttributeMaxDynamicSharedMemorySize, smF2);

    k0_detect<<<1, 256>>>((const unsigned char*)maskp);
    k1_mlp<<<EE / 32, 256>>>(rel, w1, b1, g1, be1, w2, b2, g2, be2);
    k_P<<<dim3(NN, 4), 256, smP>>>(x0, x1, nidx, maskp, b00, b01, b10, b11);
    k_F2<<<dim3(32, 16), 256, smF2>>>(w3_00, w3_01, w3_10, w3_11);
    k_E<<<128, 256>>>(x0, x1, b3_00, b3_01, b3_10, b3_11, ks0, ks1, out);
}